// round 1
// baseline (speedup 1.0000x reference)
#include <cuda_runtime.h>

// NetVLAD: B=64, C=128, K=64, N=4096
#define NV_B 64
#define NV_C 128
#define NV_K 64
#define NV_N 4096
#define NV_TN 64         // n-tile per inner iteration
#define NV_SPLIT 16      // CTAs per batch
#define NV_TILES 4       // tiles per CTA (64 tiles / 16 splits)

#define XS_PITCH 68      // padded row (floats) for the x tile
#define LT_PITCH 68      // padded row (floats) for logits/softmax tile
#define SMEM_A_BYTES ((NV_C*NV_K + NV_C*XS_PITCH + NV_TN*LT_PITCH) * 4)

// scratch: partial vlad sums + partial a-sums, indexed by blockIdx (= b*16+s)
__device__ float g_pvlad[(size_t)NV_B * NV_SPLIT * NV_K * NV_C]; // 32 MB
__device__ float g_pasum[NV_B * NV_SPLIT * NV_K];

typedef unsigned long long u64;

__device__ __forceinline__ u64 pack2(float x){
    u64 r; asm("mov.b64 %0,{%1,%1};" : "=l"(r) : "f"(x)); return r;
}
__device__ __forceinline__ u64 packab(float a, float b){
    u64 r; asm("mov.b64 %0,{%1,%2};" : "=l"(r) : "f"(a), "f"(b)); return r;
}
__device__ __forceinline__ void ffma2(u64 &d, u64 a, u64 b){
    asm("fma.rn.f32x2 %0,%1,%2,%0;" : "+l"(d) : "l"(a), "l"(b));
}
__device__ __forceinline__ float2 unpack2(u64 v){
    float2 r; asm("mov.b64 {%0,%1},%2;" : "=f"(r.x), "=f"(r.y) : "l"(v)); return r;
}

// ---------------------------------------------------------------------------
// Kernel A: per (batch, n-split): logits GEMM -> softmax -> vlad-partial GEMM
// ---------------------------------------------------------------------------
__global__ __launch_bounds__(256, 2)
void netvlad_main(const float* __restrict__ x, const float* __restrict__ conv_w)
{
    extern __shared__ float sm[];
    float* Ws = sm;                        // [C][K]  = conv_w transposed
    float* Xs = sm + NV_C * NV_K;          // [C][XS_PITCH] x tile (n contiguous)
    float* Lt = Xs + NV_C * XS_PITCH;      // [TN][LT_PITCH] logits, n-major

    const int tid = threadIdx.x;
    const int b   = blockIdx.x >> 4;
    const int s   = blockIdx.x & 15;

    // load conv_w transposed into smem (once per CTA; ordered by first sync)
    for (int i = tid; i < NV_K * NV_C; i += 256) {
        int k = i >> 7, c = i & 127;
        Ws[c * NV_K + k] = conv_w[i];
    }

    const int lty = tid >> 4, ltx = tid & 15;   // 16x16 thread grid
    const int g1k0 = lty * 4, g1n0 = ltx * 4;   // GEMM1: 4k x 4n per thread

    // GEMM2 accumulators: acc[i][j] ~ (k = 4*lty+i, c = ltx + 16*j), paired over n
    u64 acc[4][8];
    #pragma unroll
    for (int i = 0; i < 4; i++)
        #pragma unroll
        for (int j = 0; j < 8; j++) acc[i][j] = 0ULL;
    float asum0 = 0.f, asum1 = 0.f, asum2 = 0.f, asum3 = 0.f;

    const float* xb = x + (size_t)b * NV_C * NV_N;

    for (int tt = 0; tt < NV_TILES; tt++) {
        const int n0g = (s * NV_TILES + tt) * NV_TN;
        __syncthreads();   // previous GEMM2 done (and Ws ready on iter 0)

        // ---- load x tile: Xs[c][n] (rows padded to 68 floats) ----
        #pragma unroll
        for (int r = 0; r < 8; r++) {
            int q = tid + 256 * r;
            int c = q >> 4, nq = q & 15;
            float4 v = *(const float4*)(xb + (size_t)c * NV_N + n0g + 4 * nq);
            *(float4*)(Xs + c * XS_PITCH + 4 * nq) = v;
        }
        __syncthreads();

        // ---- GEMM1: L[k][n] = sum_c W[k][c] * x[c][n], f32x2-packed over n ----
        {
            u64 la[4][2];
            #pragma unroll
            for (int i = 0; i < 4; i++) { la[i][0] = 0ULL; la[i][1] = 0ULL; }
            #pragma unroll 4
            for (int c = 0; c < NV_C; c++) {
                float4 wv = *(const float4*)(Ws + c * NV_K + g1k0);
                float4 xv = *(const float4*)(Xs + c * XS_PITCH + g1n0);
                u64 xp0 = packab(xv.x, xv.y);
                u64 xp1 = packab(xv.z, xv.w);
                u64 w0 = pack2(wv.x), w1 = pack2(wv.y), w2 = pack2(wv.z), w3 = pack2(wv.w);
                ffma2(la[0][0], w0, xp0); ffma2(la[0][1], w0, xp1);
                ffma2(la[1][0], w1, xp0); ffma2(la[1][1], w1, xp1);
                ffma2(la[2][0], w2, xp0); ffma2(la[2][1], w2, xp1);
                ffma2(la[3][0], w3, xp0); ffma2(la[3][1], w3, xp1);
            }
            // store transposed: Lt[n][k]
            float l[4][4];
            #pragma unroll
            for (int i = 0; i < 4; i++) {
                float2 p0 = unpack2(la[i][0]);
                float2 p1 = unpack2(la[i][1]);
                l[i][0] = p0.x; l[i][1] = p0.y; l[i][2] = p1.x; l[i][3] = p1.y;
            }
            #pragma unroll
            for (int j = 0; j < 4; j++)
                *(float4*)(Lt + (g1n0 + j) * LT_PITCH + g1k0) =
                    make_float4(l[0][j], l[1][j], l[2][j], l[3][j]);
        }
        __syncthreads();

        // ---- softmax over k (row of Lt), 2 threads per n-row ----
        if (tid < 128) {
            int n = tid >> 1, h = tid & 1;
            float* row = Lt + n * LT_PITCH + h * 32;
            float4 v[8];
            float m = -1e30f;
            #pragma unroll
            for (int i2 = 0; i2 < 8; i2++) {
                v[i2] = *(float4*)(row + 4 * i2);
                m = fmaxf(m, fmaxf(fmaxf(v[i2].x, v[i2].y), fmaxf(v[i2].z, v[i2].w)));
            }
            m = fmaxf(m, __shfl_xor_sync(0xffffffffu, m, 1));
            float ss = 0.f;
            #pragma unroll
            for (int i2 = 0; i2 < 8; i2++) {
                v[i2].x = __expf(v[i2].x - m);
                v[i2].y = __expf(v[i2].y - m);
                v[i2].z = __expf(v[i2].z - m);
                v[i2].w = __expf(v[i2].w - m);
                ss += (v[i2].x + v[i2].y) + (v[i2].z + v[i2].w);
            }
            ss += __shfl_xor_sync(0xffffffffu, ss, 1);
            float inv = 1.0f / ss;
            #pragma unroll
            for (int i2 = 0; i2 < 8; i2++) {
                v[i2].x *= inv; v[i2].y *= inv; v[i2].z *= inv; v[i2].w *= inv;
                *(float4*)(row + 4 * i2) = v[i2];
            }
        }
        __syncthreads();

        // ---- GEMM2: acc[k][c] += sum_n a[k][n]*x[c][n], f32x2-paired over n ----
        #pragma unroll 2
        for (int nc = 0; nc < 32; nc++) {
            float4 a0 = *(const float4*)(Lt + (2 * nc + 0) * LT_PITCH + g1k0);
            float4 a1 = *(const float4*)(Lt + (2 * nc + 1) * LT_PITCH + g1k0);
            u64 ap0 = packab(a0.x, a1.x);
            u64 ap1 = packab(a0.y, a1.y);
            u64 ap2 = packab(a0.z, a1.z);
            u64 ap3 = packab(a0.w, a1.w);
            if (ltx == 0) {   // a-column sums (each k owned by exactly one thread)
                asum0 += a0.x + a1.x;
                asum1 += a0.y + a1.y;
                asum2 += a0.z + a1.z;
                asum3 += a0.w + a1.w;
            }
            #pragma unroll
            for (int j = 0; j < 8; j++) {
                u64 xp = *(const u64*)(Xs + (ltx + 16 * j) * XS_PITCH + 2 * nc);
                ffma2(acc[0][j], ap0, xp);
                ffma2(acc[1][j], ap1, xp);
                ffma2(acc[2][j], ap2, xp);
                ffma2(acc[3][j], ap3, xp);
            }
        }
    }

    // ---- write partials (each (k,c) owned by exactly one thread) ----
    float* pv = g_pvlad + (size_t)blockIdx.x * (NV_K * NV_C);
    #pragma unroll
    for (int i = 0; i < 4; i++)
        #pragma unroll
        for (int j = 0; j < 8; j++) {
            float2 p = unpack2(acc[i][j]);
            pv[(g1k0 + i) * NV_C + ltx + 16 * j] = p.x + p.y;
        }
    if (ltx == 0) {
        float* pa = g_pasum + blockIdx.x * NV_K + g1k0;
        pa[0] = asum0; pa[1] = asum1; pa[2] = asum2; pa[3] = asum3;
    }
}

// ---------------------------------------------------------------------------
// Kernel B: reduce splits, subtract asum*centroid, intra + global L2 normalize
// ---------------------------------------------------------------------------
__global__ __launch_bounds__(256)
void netvlad_finalize(const float* __restrict__ centroids, float* __restrict__ out)
{
    __shared__ float vbuf[NV_K * NV_C];
    __shared__ float wpart[NV_K][4];
    __shared__ float asumt[NV_K];
    __shared__ float invrow[NV_K];
    __shared__ float g2[2];

    const int b = blockIdx.x, t = threadIdx.x;
    const int w = t >> 5, lane = t & 31;

    if (t < NV_K) {
        float sum = 0.f;
        #pragma unroll
        for (int sp = 0; sp < NV_SPLIT; sp++)
            sum += g_pasum[(b * NV_SPLIT + sp) * NV_K + t];
        asumt[t] = sum;
    }
    __syncthreads();

    const size_t base = (size_t)b * NV_SPLIT * (NV_K * NV_C);
    for (int i = 0; i < 32; i++) {
        int flat = i * 256 + t;
        int k = flat >> 7;
        float v = 0.f;
        #pragma unroll
        for (int sp = 0; sp < NV_SPLIT; sp++)
            v += g_pvlad[base + (size_t)sp * (NV_K * NV_C) + flat];
        v -= asumt[k] * centroids[flat];
        vbuf[flat] = v;
        float v2 = v * v;
        #pragma unroll
        for (int o = 16; o > 0; o >>= 1)
            v2 += __shfl_xor_sync(0xffffffffu, v2, o);
        // each warp covers 32 elements of one k-row; each k hit by exactly 4 warps total
        if (lane == 0) wpart[k][w & 3] = v2;
    }
    __syncthreads();

    if (t < NV_K) {
        float rs  = wpart[t][0] + wpart[t][1] + wpart[t][2] + wpart[t][3];
        float rn  = sqrtf(rs);
        float inv = 1.0f / fmaxf(rn, 1e-12f);
        invrow[t] = inv;
        float c1 = rn * inv;          // == 1 when rn >= eps (matches reference)
        float contrib = c1 * c1;
        #pragma unroll
        for (int o = 16; o > 0; o >>= 1)
            contrib += __shfl_xor_sync(0xffffffffu, contrib, o);
        if (lane == 0) g2[w] = contrib;
    }
    __syncthreads();

    const float ginv = 1.0f / fmaxf(sqrtf(g2[0] + g2[1]), 1e-12f);
    float* ob = out + (size_t)b * (NV_K * NV_C);
    for (int i = 0; i < 32; i++) {
        int flat = i * 256 + t;
        ob[flat] = vbuf[flat] * invrow[flat >> 7] * ginv;
    }
}

// ---------------------------------------------------------------------------
extern "C" void kernel_launch(void* const* d_in, const int* in_sizes, int n_in,
                              void* d_out, int out_size)
{
    const float* x         = (const float*)d_in[0];
    const float* conv_w    = (const float*)d_in[1];
    const float* centroids = (const float*)d_in[2];
    float* out = (float*)d_out;

    cudaFuncSetAttribute(netvlad_main,
                         cudaFuncAttributeMaxDynamicSharedMemorySize, SMEM_A_BYTES);
    netvlad_main<<<NV_B * NV_SPLIT, 256, SMEM_A_BYTES>>>(x, conv_w);
    netvlad_finalize<<<NV_B, 256>>>(centroids, out);
}